// round 7
// baseline (speedup 1.0000x reference)
#include <cuda_runtime.h>
#include <stdint.h>

// ============================================================================
// HopfieldNet — reference model (Round 7):
//   PRNG:    JAX partitionable threefry: bits[t] = o0 ^ o1 of tf2x32(key,(0,t))
//   GEMM:    exact fp32, per-element single ascending-k FMA chain
//   sigmoid: p = 1/(1+exp(-z))  [exp form, libdevice expf, div.rn]
//   z:       (2*h) * (1/T)     [XLA simplifier: divide-by-const -> mul-recip]
// ============================================================================

#define NB   65536
#define ND   1024
#define NTOT (NB * ND)

#define BM 128
#define BN 128
#define BKT 16
#define TM 8
#define TN 8
#define APAD 4

__device__ float g_W [ND * ND];
__device__ float g_xA[NTOT];
__device__ float g_xB[NTOT];

// ---------------------------------------------------------------- threefry
__device__ __forceinline__ void tf2x32(uint32_t k0, uint32_t k1,
                                       uint32_t c0, uint32_t c1,
                                       uint32_t &o0, uint32_t &o1) {
    uint32_t ks2 = k0 ^ k1 ^ 0x1BD11BDAu;
    uint32_t x0 = c0 + k0;
    uint32_t x1 = c1 + k1;
#define TF_R(r) { x0 += x1; x1 = __funnelshift_l(x1, x1, (r)); x1 ^= x0; }
    TF_R(13) TF_R(15) TF_R(26) TF_R(6)   x0 += k1;  x1 += ks2 + 1u;
    TF_R(17) TF_R(29) TF_R(16) TF_R(24)  x0 += ks2; x1 += k0  + 2u;
    TF_R(13) TF_R(15) TF_R(26) TF_R(6)   x0 += k0;  x1 += k1  + 3u;
    TF_R(17) TF_R(29) TF_R(16) TF_R(24)  x0 += k1;  x1 += ks2 + 4u;
    TF_R(13) TF_R(15) TF_R(26) TF_R(6)   x0 += ks2; x1 += k0  + 5u;
#undef TF_R
    o0 = x0; o1 = x1;
}

__device__ __forceinline__ float jax_uniform(uint32_t k0, uint32_t k1, uint32_t t) {
    uint32_t o0, o1;
    tf2x32(k0, k1, 0u, t, o0, o1);
    uint32_t bits = o0 ^ o1;
    return __uint_as_float((bits >> 9) | 0x3f800000u) - 1.0f;
}

// stochastic activation: z = (2h)*rT;  p = 1/(1+exp(-z));  u<p ? 1 : -1
__device__ __forceinline__ float act(float h, float rT,
                                     uint32_t k0, uint32_t k1, uint32_t t) {
    float u = jax_uniform(k0, k1, t);
    float z = __fmul_rn(__fmul_rn(2.0f, h), rT);   // mul-by-reciprocal (XLA)
    float e = expf(-z);                            // libdevice __nv_expf
    float p = __fdiv_rn(1.0f, __fadd_rn(1.0f, e));
    return (u < p) ? 1.0f : -1.0f;
}

// ---------------------------------------------------------------- W = Wu+Wu^T
__global__ void prep_W(const float* __restrict__ Wu) {
    int idx = blockIdx.x * blockDim.x + threadIdx.x;
    int k = idx >> 10;
    int j = idx & 1023;
    g_W[idx] = __fadd_rn(Wu[idx], Wu[j * ND + k]);
}

// ---------------------------------------------------------------- fused step
__global__ void __launch_bounds__(256)
hop_step(const float* __restrict__ X, float* __restrict__ O,
         uint32_t k0, uint32_t k1, float rT) {
    __shared__ float As[BKT][BM + APAD];
    __shared__ float Bs[BKT][BN];

    const int tid = threadIdx.x;
    const int tx  = tid & 15;
    const int ty  = tid >> 4;

    const int row0 = blockIdx.y * BM;
    const int col0 = blockIdx.x * BN;

    float acc[TM][TN];
#pragma unroll
    for (int m = 0; m < TM; m++)
#pragma unroll
        for (int n = 0; n < TN; n++) acc[m][n] = 0.0f;

    for (int kt = 0; kt < ND; kt += BKT) {
#pragma unroll
        for (int l = 0; l < 2; l++) {
            int e = tid * 2 + l;
            int r = e >> 2;
            int c = (e & 3) * 4;
            float4 v = *(const float4*)&X[(size_t)(row0 + r) * ND + kt + c];
            As[c + 0][r] = v.x; As[c + 1][r] = v.y;
            As[c + 2][r] = v.z; As[c + 3][r] = v.w;
        }
#pragma unroll
        for (int l = 0; l < 2; l++) {
            int e  = tid * 2 + l;
            int kr = e >> 5;
            int c  = (e & 31) * 4;
            *(float4*)&Bs[kr][c] =
                *(const float4*)&g_W[(size_t)(kt + kr) * ND + col0 + c];
        }
        __syncthreads();

#pragma unroll
        for (int kk = 0; kk < BKT; kk++) {          // strict ascending k
            float a[TM], b[TN];
#pragma unroll
            for (int m = 0; m < TM; m++) a[m] = As[kk][ty * TM + m];
#pragma unroll
            for (int n = 0; n < TN; n++) b[n] = Bs[kk][tx * TN + n];
#pragma unroll
            for (int m = 0; m < TM; m++)
#pragma unroll
                for (int n = 0; n < TN; n++)
                    acc[m][n] = __fmaf_rn(a[m], b[n], acc[m][n]);
        }
        __syncthreads();
    }

#pragma unroll
    for (int m = 0; m < TM; m++) {
        const int gi = row0 + ty * TM + m;
#pragma unroll
        for (int n = 0; n < TN; n++) {
            const int gj = col0 + tx * TN + n;
            const uint32_t t = ((uint32_t)gi << 10) | (uint32_t)gj;
            O[(size_t)gi * ND + gj] = act(acc[m][n], rT, k0, k1, t);
        }
    }
}

// ---------------------------------------------------------------- host side
static inline uint32_t h_rotl(uint32_t x, int r) { return (x << r) | (x >> (32 - r)); }
static void h_tf2x32(uint32_t k0, uint32_t k1, uint32_t c0, uint32_t c1,
                     uint32_t* o0, uint32_t* o1) {
    uint32_t ks2 = k0 ^ k1 ^ 0x1BD11BDAu;
    uint32_t x0 = c0 + k0, x1 = c1 + k1;
#define HTF_R(r) { x0 += x1; x1 = h_rotl(x1, (r)); x1 ^= x0; }
    HTF_R(13) HTF_R(15) HTF_R(26) HTF_R(6)   x0 += k1;  x1 += ks2 + 1u;
    HTF_R(17) HTF_R(29) HTF_R(16) HTF_R(24)  x0 += ks2; x1 += k0  + 2u;
    HTF_R(13) HTF_R(15) HTF_R(26) HTF_R(6)   x0 += k0;  x1 += k1  + 3u;
    HTF_R(17) HTF_R(29) HTF_R(16) HTF_R(24)  x0 += k1;  x1 += ks2 + 4u;
    HTF_R(13) HTF_R(15) HTF_R(26) HTF_R(6)   x0 += ks2; x1 += k0  + 5u;
#undef HTF_R
    *o0 = x0; *o1 = x1;
}

extern "C" void kernel_launch(void* const* d_in, const int* in_sizes, int n_in,
                              void* d_out, int out_size) {
    const float* x0 = (const float*)d_in[0];   // (65536, 1024) f32
    const float* Wu = (const float*)d_in[1];   // (1024, 1024)  f32

    float *xA, *xB;
    cudaGetSymbolAddress((void**)&xA, g_xA);
    cudaGetSymbolAddress((void**)&xB, g_xB);

    prep_W<<<(ND * ND) / 256, 256>>>(Wu);

    uint32_t keys[10][2];
    for (int i = 0; i < 10; i++)
        h_tf2x32(0u, 42u, 0u, (uint32_t)i, &keys[i][0], &keys[i][1]);

    dim3 grid(ND / BN, NB / BM);   // (8, 512)
    const float* src = x0;
    for (int i = 0; i < 10; i++) {
        // T = f32(1/(2i+1)); XLA: divide(x, T) -> multiply(x, f32(1/T))
        volatile float T  = (float)(1.0 / (double)(2 * i + 1));
        volatile float rT = 1.0f / T;                 // f32 reciprocal constant
        float* dst = (i == 9) ? (float*)d_out : (((i & 1) == 0) ? xA : xB);
        hop_step<<<grid, 256>>>(src, dst, keys[i][0], keys[i][1], rT);
        src = dst;
    }
}

// round 8
// speedup vs baseline: 1.6354x; 1.6354x over previous
#include <cuda_runtime.h>
#include <stdint.h>

// ============================================================================
// HopfieldNet — bit-exact reference model (locked in Round 7):
//   PRNG:    JAX partitionable threefry: bits[t] = o0 ^ o1 of tf2x32(key,(0,t))
//   GEMM:    exact fp32, per-element single ascending-k FMA chain
//   sigmoid: p = 1/(1+exp(-z)), z = (2*h)*(1/T), libdevice expf, div.rn
// Speed: FFMA2 (fma.rn.f32x2) packed math — IEEE rn per 32-bit lane, so each
// element's k-chain rounding is IDENTICAL to scalar FFMA. 2x FMA throughput.
// ============================================================================

#define NB   65536
#define ND   1024
#define NTOT (NB * ND)

#define BM 128
#define BN 128
#define BKT 16
#define TM 8
#define TN 8
#define APAD 4

__device__ float g_W [ND * ND];
__device__ float g_xA[NTOT];
__device__ float g_xB[NTOT];

// ---------------------------------------------------------------- threefry
__device__ __forceinline__ void tf2x32(uint32_t k0, uint32_t k1,
                                       uint32_t c0, uint32_t c1,
                                       uint32_t &o0, uint32_t &o1) {
    uint32_t ks2 = k0 ^ k1 ^ 0x1BD11BDAu;
    uint32_t x0 = c0 + k0;
    uint32_t x1 = c1 + k1;
#define TF_R(r) { x0 += x1; x1 = __funnelshift_l(x1, x1, (r)); x1 ^= x0; }
    TF_R(13) TF_R(15) TF_R(26) TF_R(6)   x0 += k1;  x1 += ks2 + 1u;
    TF_R(17) TF_R(29) TF_R(16) TF_R(24)  x0 += ks2; x1 += k0  + 2u;
    TF_R(13) TF_R(15) TF_R(26) TF_R(6)   x0 += k0;  x1 += k1  + 3u;
    TF_R(17) TF_R(29) TF_R(16) TF_R(24)  x0 += k1;  x1 += ks2 + 4u;
    TF_R(13) TF_R(15) TF_R(26) TF_R(6)   x0 += ks2; x1 += k0  + 5u;
#undef TF_R
    o0 = x0; o1 = x1;
}

__device__ __forceinline__ float jax_uniform(uint32_t k0, uint32_t k1, uint32_t t) {
    uint32_t o0, o1;
    tf2x32(k0, k1, 0u, t, o0, o1);
    uint32_t bits = o0 ^ o1;
    return __uint_as_float((bits >> 9) | 0x3f800000u) - 1.0f;
}

__device__ __forceinline__ float act(float h, float rT,
                                     uint32_t k0, uint32_t k1, uint32_t t) {
    float u = jax_uniform(k0, k1, t);
    float z = __fmul_rn(__fmul_rn(2.0f, h), rT);
    float e = expf(-z);
    float p = __fdiv_rn(1.0f, __fadd_rn(1.0f, e));
    return (u < p) ? 1.0f : -1.0f;
}

// ---------------------------------------------------------------- f32x2 ops
__device__ __forceinline__ uint64_t dup_f32x2(float a) {
    uint64_t r;
    asm("mov.b64 %0, {%1, %1};" : "=l"(r) : "f"(a));
    return r;
}
__device__ __forceinline__ void ffma2(uint64_t &acc, uint64_t a2, uint64_t b2) {
    // lanewise fp32 fma, round-to-nearest-even each lane — bit-exact vs scalar
    asm("fma.rn.f32x2 %0, %1, %2, %0;" : "+l"(acc) : "l"(a2), "l"(b2));
}
__device__ __forceinline__ void unpack_f32x2(uint64_t v, float &lo, float &hi) {
    asm("mov.b64 {%0, %1}, %2;" : "=f"(lo), "=f"(hi) : "l"(v));
}

// ---------------------------------------------------------------- W = Wu+Wu^T
__global__ void prep_W(const float* __restrict__ Wu) {
    int idx = blockIdx.x * blockDim.x + threadIdx.x;
    int k = idx >> 10;
    int j = idx & 1023;
    g_W[idx] = __fadd_rn(Wu[idx], Wu[j * ND + k]);
}

// ---------------------------------------------------------------- fused step
// 256 threads, 8x8 outputs/thread; inner product via packed FFMA2:
// acc pair = (n even, n odd); b pairs reinterpreted straight from float4 LDS.
__global__ void __launch_bounds__(256)
hop_step(const float* __restrict__ X, float* __restrict__ O,
         uint32_t k0, uint32_t k1, float rT) {
    __shared__ float As[BKT][BM + APAD];
    __shared__ float Bs[BKT][BN];

    const int tid = threadIdx.x;
    const int tx  = tid & 15;
    const int ty  = tid >> 4;

    const int row0 = blockIdx.y * BM;
    const int col0 = blockIdx.x * BN;

    uint64_t acc[TM][TN / 2];
#pragma unroll
    for (int m = 0; m < TM; m++)
#pragma unroll
        for (int n = 0; n < TN / 2; n++) acc[m][n] = 0ull;

    for (int kt = 0; kt < ND; kt += BKT) {
#pragma unroll
        for (int l = 0; l < 2; l++) {
            int e = tid * 2 + l;
            int r = e >> 2;
            int c = (e & 3) * 4;
            float4 v = *(const float4*)&X[(size_t)(row0 + r) * ND + kt + c];
            As[c + 0][r] = v.x; As[c + 1][r] = v.y;
            As[c + 2][r] = v.z; As[c + 3][r] = v.w;
        }
#pragma unroll
        for (int l = 0; l < 2; l++) {
            int e  = tid * 2 + l;
            int kr = e >> 5;
            int c  = (e & 31) * 4;
            *(float4*)&Bs[kr][c] =
                *(const float4*)&g_W[(size_t)(kt + kr) * ND + col0 + c];
        }
        __syncthreads();

#pragma unroll
        for (int kk = 0; kk < BKT; kk++) {     // strict ascending k
            // a: 8 consecutive m values -> duplicate into both f32x2 lanes
            float4 av0 = *(const float4*)&As[kk][ty * TM];
            float4 av1 = *(const float4*)&As[kk][ty * TM + 4];
            uint64_t a2[TM];
            a2[0] = dup_f32x2(av0.x); a2[1] = dup_f32x2(av0.y);
            a2[2] = dup_f32x2(av0.z); a2[3] = dup_f32x2(av0.w);
            a2[4] = dup_f32x2(av1.x); a2[5] = dup_f32x2(av1.y);
            a2[6] = dup_f32x2(av1.z); a2[7] = dup_f32x2(av1.w);
            // b: 8 consecutive n values = 4 natural f32x2 pairs (lo = even n)
            float4 bv0 = *(const float4*)&Bs[kk][tx * TN];
            float4 bv1 = *(const float4*)&Bs[kk][tx * TN + 4];
            uint64_t b2[TN / 2];
            b2[0] = ((const uint64_t*)&bv0)[0];
            b2[1] = ((const uint64_t*)&bv0)[1];
            b2[2] = ((const uint64_t*)&bv1)[0];
            b2[3] = ((const uint64_t*)&bv1)[1];
#pragma unroll
            for (int m = 0; m < TM; m++)
#pragma unroll
                for (int n = 0; n < TN / 2; n++)
                    ffma2(acc[m][n], a2[m], b2[n]);
        }
        __syncthreads();
    }

    // epilogue: unpack pairs, threefry + logistic + sign, vector stores
#pragma unroll
    for (int m = 0; m < TM; m++) {
        const int gi = row0 + ty * TM + m;
        const int gj0 = col0 + tx * TN;
        float out[TN];
#pragma unroll
        for (int n = 0; n < TN / 2; n++) {
            float lo, hi;
            unpack_f32x2(acc[m][n], lo, hi);
            uint32_t tl = ((uint32_t)gi << 10) | (uint32_t)(gj0 + 2 * n);
            out[2 * n]     = act(lo, rT, k0, k1, tl);
            out[2 * n + 1] = act(hi, rT, k0, k1, tl + 1);
        }
        float4* dst = (float4*)&O[(size_t)gi * ND + gj0];
        dst[0] = make_float4(out[0], out[1], out[2], out[3]);
        dst[1] = make_float4(out[4], out[5], out[6], out[7]);
    }
}

// ---------------------------------------------------------------- host side
static inline uint32_t h_rotl(uint32_t x, int r) { return (x << r) | (x >> (32 - r)); }
static void h_tf2x32(uint32_t k0, uint32_t k1, uint32_t c0, uint32_t c1,
                     uint32_t* o0, uint32_t* o1) {
    uint32_t ks2 = k0 ^ k1 ^ 0x1BD11BDAu;
    uint32_t x0 = c0 + k0, x1 = c1 + k1;
#define HTF_R(r) { x0 += x1; x1 = h_rotl(x1, (r)); x1 ^= x0; }
    HTF_R(13) HTF_R(15) HTF_R(26) HTF_R(6)   x0 += k1;  x1 += ks2 + 1u;
    HTF_R(17) HTF_R(29) HTF_R(16) HTF_R(24)  x0 += ks2; x1 += k0  + 2u;
    HTF_R(13) HTF_R(15) HTF_R(26) HTF_R(6)   x0 += k0;  x1 += k1  + 3u;
    HTF_R(17) HTF_R(29) HTF_R(16) HTF_R(24)  x0 += k1;  x1 += ks2 + 4u;
    HTF_R(13) HTF_R(15) HTF_R(26) HTF_R(6)   x0 += ks2; x1 += k0  + 5u;
#undef HTF_R
    *o0 = x0; *o1 = x1;
}

extern "C" void kernel_launch(void* const* d_in, const int* in_sizes, int n_in,
                              void* d_out, int out_size) {
    const float* x0 = (const float*)d_in[0];   // (65536, 1024) f32
    const float* Wu = (const float*)d_in[1];   // (1024, 1024)  f32

    float *xA, *xB;
    cudaGetSymbolAddress((void**)&xA, g_xA);
    cudaGetSymbolAddress((void**)&xB, g_xB);

    prep_W<<<(ND * ND) / 256, 256>>>(Wu);

    uint32_t keys[10][2];
    for (int i = 0; i < 10; i++)
        h_tf2x32(0u, 42u, 0u, (uint32_t)i, &keys[i][0], &keys[i][1]);

    dim3 grid(ND / BN, NB / BM);   // (8, 512)
    const float* src = x0;
    for (int i = 0; i < 10; i++) {
        volatile float T  = (float)(1.0 / (double)(2 * i + 1));
        volatile float rT = 1.0f / T;
        float* dst = (i == 9) ? (float*)d_out : (((i & 1) == 0) ? xA : xB);
        hop_step<<<grid, 256>>>(src, dst, keys[i][0], keys[i][1], rT);
        src = dst;
    }
}